// round 1
// baseline (speedup 1.0000x reference)
#include <cuda_runtime.h>

#define B_MAX 256

// Scratch (static device globals — no allocation in kernel_launch)
__device__ float g_emb[B_MAX * 3 * 32 * 32 * 32];  // [b][c][i][t][j]
__device__ float g_sig[B_MAX * 3 * 32 * 32 * 32];  // sigmoid(LN(y-branch)) [b][c][i][t][j]
__device__ float g_sg2[B_MAX * 3 * 32 * 32];       // sigmoid(LN(x-branch)) [b][c][tok][feat]

__device__ __forceinline__ float sigmoid_(float v) { return 1.0f / (1.0f + __expf(-v)); }

// ---------------------------------------------------------------------------
// K1: emb[b,c,i,t,j] = sum_d x[b,c,t,d,i] * pos_y[c,j,d]
// One CTA per (b,c,t). Coalesced read of x tile + coalesced (128B-chunk) writes.
// ---------------------------------------------------------------------------
__global__ void __launch_bounds__(256) k_emb(const float* __restrict__ x,
                                             const float* __restrict__ pos)
{
    __shared__ float xs[32 * 33]; // xs[d][i]
    __shared__ float ps[32 * 36]; // ps[j][d], stride 36 -> 16B aligned rows

    int bct = blockIdx.x;
    int t   = bct & 31;
    int bc  = bct >> 5;
    int c   = bc % 3;
    int tid = threadIdx.x;

    float4 xv = ((const float4*)(x + (size_t)bct * 1024))[tid];
    int rd = tid >> 3, c0 = (tid & 7) * 4;
    xs[rd * 33 + c0 + 0] = xv.x; xs[rd * 33 + c0 + 1] = xv.y;
    xs[rd * 33 + c0 + 2] = xv.z; xs[rd * 33 + c0 + 3] = xv.w;

    float4 pv = ((const float4*)(pos + c * 1024))[tid];
    ps[rd * 36 + c0 + 0] = pv.x; ps[rd * 36 + c0 + 1] = pv.y;
    ps[rd * 36 + c0 + 2] = pv.z; ps[rd * 36 + c0 + 3] = pv.w;
    __syncthreads();

    int i = tid >> 3, j0 = (tid & 7) * 4;
    float xc[32];
#pragma unroll
    for (int d = 0; d < 32; d++) xc[d] = xs[d * 33 + i];

    float a0 = 0.f, a1 = 0.f, a2 = 0.f, a3 = 0.f;
#pragma unroll
    for (int d4 = 0; d4 < 8; d4++) {
        float4 p;
        p = *(const float4*)(ps + (j0 + 0) * 36 + 4 * d4);
        a0 = fmaf(xc[4*d4], p.x, a0); a0 = fmaf(xc[4*d4+1], p.y, a0);
        a0 = fmaf(xc[4*d4+2], p.z, a0); a0 = fmaf(xc[4*d4+3], p.w, a0);
        p = *(const float4*)(ps + (j0 + 1) * 36 + 4 * d4);
        a1 = fmaf(xc[4*d4], p.x, a1); a1 = fmaf(xc[4*d4+1], p.y, a1);
        a1 = fmaf(xc[4*d4+2], p.z, a1); a1 = fmaf(xc[4*d4+3], p.w, a1);
        p = *(const float4*)(ps + (j0 + 2) * 36 + 4 * d4);
        a2 = fmaf(xc[4*d4], p.x, a2); a2 = fmaf(xc[4*d4+1], p.y, a2);
        a2 = fmaf(xc[4*d4+2], p.z, a2); a2 = fmaf(xc[4*d4+3], p.w, a2);
        p = *(const float4*)(ps + (j0 + 3) * 36 + 4 * d4);
        a3 = fmaf(xc[4*d4], p.x, a3); a3 = fmaf(xc[4*d4+1], p.y, a3);
        a3 = fmaf(xc[4*d4+2], p.z, a3); a3 = fmaf(xc[4*d4+3], p.w, a3);
    }
    float4 ov = make_float4(a0, a1, a2, a3);
    *(float4*)(g_emb + ((size_t)bc * 32 + i) * 1024 + t * 32 + j0) = ov;
}

// ---------------------------------------------------------------------------
// Warp-level attention + residual + layernorm + sigmoid.
// lane = token t (32 tokens). D=32, H=8, DH=4.
// sK/sV/sQ: per-warp smem tiles, row stride 36 floats (16B aligned, low conflict).
// K/V/Q smem layout: [token][h*4+d]  -> scores/AV read one float4 per (s,h).
// ---------------------------------------------------------------------------
__device__ __forceinline__ void warp_attn(
    int lane,
    const float* __restrict__ eg,   // E tile base, row-major [t][j], 32x32
    float* __restrict__ og,         // output tile base, [t][j]
    const float* __restrict__ sW,   // Wqvk [96][32] in smem
    const float* __restrict__ sW0,  // W0 [32][32] in smem
    const float* __restrict__ sgb,  // gamma[32], beta[32]
    float* sK, float* sV, float* sQ)
{
    // cooperative coalesced load of E into sK staging
#pragma unroll
    for (int r = 0; r < 32; r++) sK[r * 36 + lane] = eg[r * 32 + lane];
    __syncwarp();

    float e[32];
#pragma unroll
    for (int j = 0; j < 8; j++) {
        float4 v = *(const float4*)(sK + lane * 36 + 4 * j);
        e[4*j] = v.x; e[4*j+1] = v.y; e[4*j+2] = v.z; e[4*j+3] = v.w;
    }

    // QKV projections: f = d*24 + which*8 + h ; store at m = h*4+d
#pragma unroll 1
    for (int m = 0; m < 32; m++) {
        int h = m >> 2, d = m & 3;
        const float4* wq = (const float4*)(sW + (d * 24 + h) * 32);
        const float4* wk = (const float4*)(sW + (d * 24 + 8 + h) * 32);
        const float4* wv = (const float4*)(sW + (d * 24 + 16 + h) * 32);
        float q0=0,q1=0,q2=0,q3=0, k0=0,k1=0,k2=0,k3=0, v0=0,v1=0,v2=0,v3=0;
#pragma unroll
        for (int j = 0; j < 8; j++) {
            float4 w;
            w = wq[j];
            q0 = fmaf(e[4*j], w.x, q0); q1 = fmaf(e[4*j+1], w.y, q1);
            q2 = fmaf(e[4*j+2], w.z, q2); q3 = fmaf(e[4*j+3], w.w, q3);
            w = wk[j];
            k0 = fmaf(e[4*j], w.x, k0); k1 = fmaf(e[4*j+1], w.y, k1);
            k2 = fmaf(e[4*j+2], w.z, k2); k3 = fmaf(e[4*j+3], w.w, k3);
            w = wv[j];
            v0 = fmaf(e[4*j], w.x, v0); v1 = fmaf(e[4*j+1], w.y, v1);
            v2 = fmaf(e[4*j+2], w.z, v2); v3 = fmaf(e[4*j+3], w.w, v3);
        }
        sQ[lane * 36 + m] = (q0 + q1) + (q2 + q3);
        sK[lane * 36 + m] = (k0 + k1) + (k2 + k3);
        sV[lane * 36 + m] = (v0 + v1) + (v2 + v3);
    }
    __syncwarp();

    // per-head softmax attention; o written back over own q row in sQ
#pragma unroll 1
    for (int h = 0; h < 8; h++) {
        float4 q = *(const float4*)(sQ + lane * 36 + 4 * h);
        float sc[32];
        float mx = -3.0e38f;
#pragma unroll
        for (int s = 0; s < 32; s++) {
            float4 k4 = *(const float4*)(sK + s * 36 + 4 * h);
            float dd = fmaf(q.x, k4.x, fmaf(q.y, k4.y, fmaf(q.z, k4.z, q.w * k4.w)));
            sc[s] = dd * 0.5f;
            mx = fmaxf(mx, sc[s]);
        }
        float sum = 0.0f;
#pragma unroll
        for (int s = 0; s < 32; s++) { float p = __expf(sc[s] - mx); sc[s] = p; sum += p; }
        float inv = 1.0f / sum;
        float a0 = 0.f, a1 = 0.f, a2 = 0.f, a3 = 0.f;
#pragma unroll
        for (int s = 0; s < 32; s++) {
            float4 v4 = *(const float4*)(sV + s * 36 + 4 * h);
            a0 = fmaf(sc[s], v4.x, a0); a1 = fmaf(sc[s], v4.y, a1);
            a2 = fmaf(sc[s], v4.z, a2); a3 = fmaf(sc[s], v4.w, a3);
        }
        float4 ov = make_float4(a0 * inv, a1 * inv, a2 * inv, a3 * inv);
        *(float4*)(sQ + lane * 36 + 4 * h) = ov;  // own row only
    }

    // gather o (own row), then sync before reusing sV for residual rows
    float o[32];
#pragma unroll
    for (int j = 0; j < 8; j++) {
        float4 v = *(const float4*)(sQ + lane * 36 + 4 * j);
        o[4*j] = v.x; o[4*j+1] = v.y; o[4*j+2] = v.z; o[4*j+3] = v.w;
    }
    __syncwarp();

    // output projection + residual
    float rr[32];
#pragma unroll
    for (int j = 0; j < 32; j++) {
        const float4* w = (const float4*)(sW0 + j * 32);
        float a = 0.f, b = 0.f, c2 = 0.f, d2 = 0.f;
#pragma unroll
        for (int k8 = 0; k8 < 8; k8++) {
            float4 w4 = w[k8];
            a  = fmaf(o[4*k8],   w4.x, a);
            b  = fmaf(o[4*k8+1], w4.y, b);
            c2 = fmaf(o[4*k8+2], w4.z, c2);
            d2 = fmaf(o[4*k8+3], w4.w, d2);
        }
        rr[j] = e[j] + ((a + b) + (c2 + d2));
    }

    // layernorm (exact two-pass like reference) + sigmoid
    float s1 = 0.f;
#pragma unroll
    for (int j = 0; j < 32; j++) s1 += rr[j];
    float mu = s1 * 0.03125f;
    float sq = 0.f;
#pragma unroll
    for (int j = 0; j < 32; j++) { float dd = rr[j] - mu; sq = fmaf(dd, dd, sq); }
    float rstd = rsqrtf(sq * 0.03125f + 1e-5f);
#pragma unroll
    for (int j = 0; j < 32; j++) {
        float v = (rr[j] - mu) * rstd * sgb[j] + sgb[32 + j];
        sV[lane * 36 + j] = sigmoid_(v);
    }
    __syncwarp();

    // cooperative coalesced store
#pragma unroll
    for (int r = 0; r < 32; r++) og[r * 32 + lane] = sV[r * 36 + lane];
}

// ---------------------------------------------------------------------------
// K2: x-branch. 1 warp per (b,c) on emb_last = emb[b,2,31]. Writes g_sg2.
// ---------------------------------------------------------------------------
#define WX 4
__global__ void __launch_bounds__(WX * 32) k_attn_x(
    const float* __restrict__ Wqvk, const float* __restrict__ W0,
    const float* __restrict__ g, const float* __restrict__ b)
{
    extern __shared__ float sm[];
    float* sW3  = sm;             // 3 * 3072
    float* sW03 = sm + 9216;      // 3 * 1024
    float* sgb  = sm + 12288;     // 64
    float* tiles = sm + 12352;    // WX * 3 * 1152

    int tid = threadIdx.x;
    int w = tid >> 5, lane = tid & 31;
    for (int k = tid; k < 2304; k += WX * 32) ((float4*)sW3)[k]  = ((const float4*)Wqvk)[k];
    for (int k = tid; k < 768;  k += WX * 32) ((float4*)sW03)[k] = ((const float4*)W0)[k];
    if (tid < 32) { sgb[tid] = g[tid]; sgb[32 + tid] = b[tid]; }
    __syncthreads();

    int lin = blockIdx.x * WX + w;   // b*3 + c
    int bb = lin / 3, c = lin % 3;
    const float* eg = g_emb + (((size_t)bb * 3 + 2) * 32 + 31) * 1024;
    float* og = g_sg2 + (size_t)lin * 1024;
    float* sK = tiles + w * 3456;
    warp_attn(lane, eg, og, sW3 + c * 3072, sW03 + c * 1024, sgb, sK, sK + 1152, sK + 2304);
}

// ---------------------------------------------------------------------------
// K3: y-branch. 1 warp per (b,c,i). Writes g_sig.
// ---------------------------------------------------------------------------
#define WY 4
__global__ void __launch_bounds__(WY * 32) k_attn_y(
    const float* __restrict__ Wqvk, const float* __restrict__ W0,
    const float* __restrict__ g, const float* __restrict__ b)
{
    extern __shared__ float sm[];
    float* sW  = sm;            // 3072
    float* sW0 = sm + 3072;     // 1024
    float* sgb = sm + 4096;     // 64
    float* tiles = sm + 4160;   // WY * 3 * 1152

    int tid = threadIdx.x;
    int w = tid >> 5, lane = tid & 31;
    int bc = blockIdx.x >> 3;     // 8 i-blocks of WY=4
    int iblk = blockIdx.x & 7;
    int c = bc % 3;

    for (int k = tid; k < 768; k += WY * 32) ((float4*)sW)[k]  = ((const float4*)(Wqvk + c * 3072))[k];
    for (int k = tid; k < 256; k += WY * 32) ((float4*)sW0)[k] = ((const float4*)(W0 + c * 1024))[k];
    if (tid < 32) { sgb[tid] = g[tid]; sgb[32 + tid] = b[tid]; }
    __syncthreads();

    int i = iblk * WY + w;
    const float* eg = g_emb + ((size_t)bc * 32 + i) * 1024;
    float* og       = g_sig + ((size_t)bc * 32 + i) * 1024;
    float* sK = tiles + w * 3456;
    warp_attn(lane, eg, og, sW, sW0, sgb, sK, sK + 1152, sK + 2304);
}

// ---------------------------------------------------------------------------
// K4: out[b,c,t,j,i] = sg2[b,c,i,t] * g_sig[b,c,i,t,j] * x[b,c,t,j,i]
// One CTA per (b,c,t); gate tile transposed through smem for coalescing.
// ---------------------------------------------------------------------------
__global__ void __launch_bounds__(256) k_final(const float* __restrict__ x,
                                               float* __restrict__ out)
{
    __shared__ float gs[32 * 33]; // gs[i][j]
    __shared__ float ss[32];      // sg2[i]
    int bct = blockIdx.x;
    int t = bct & 31;
    int bc = bct >> 5;
    int tid = threadIdx.x;

    int i = tid >> 3, j0 = (tid & 7) * 4;
    float4 gv = *(const float4*)(g_sig + ((size_t)bc * 32 + i) * 1024 + t * 32 + j0);
    gs[i * 33 + j0 + 0] = gv.x; gs[i * 33 + j0 + 1] = gv.y;
    gs[i * 33 + j0 + 2] = gv.z; gs[i * 33 + j0 + 3] = gv.w;
    if (tid < 32) ss[tid] = g_sg2[(size_t)bc * 1024 + tid * 32 + t];
    __syncthreads();

    float4 xv = ((const float4*)(x + (size_t)bct * 1024))[tid];
    int jj = tid >> 3, i0 = (tid & 7) * 4;
    float4 ov;
    ov.x = ss[i0 + 0] * gs[(i0 + 0) * 33 + jj] * xv.x;
    ov.y = ss[i0 + 1] * gs[(i0 + 1) * 33 + jj] * xv.y;
    ov.z = ss[i0 + 2] * gs[(i0 + 2) * 33 + jj] * xv.z;
    ov.w = ss[i0 + 3] * gs[(i0 + 3) * 33 + jj] * xv.w;
    ((float4*)(out + (size_t)bct * 1024))[tid] = ov;
}

// ---------------------------------------------------------------------------
extern "C" void kernel_launch(void* const* d_in, const int* in_sizes, int n_in,
                              void* d_out, int out_size)
{
    const float* x   = (const float*)d_in[0];
    const float* pos = (const float*)d_in[1];
    const float* Wqy = (const float*)d_in[2];
    const float* W0y = (const float*)d_in[3];
    const float* gy  = (const float*)d_in[4];
    const float* by  = (const float*)d_in[5];
    const float* Wqx = (const float*)d_in[6];
    const float* W0x = (const float*)d_in[7];
    const float* gx  = (const float*)d_in[8];
    const float* bx  = (const float*)d_in[9];
    float* out = (float*)d_out;

    int B = in_sizes[0] / 98304;  // 3*32*32*32

    const int SMEM_Y = (4160 + WY * 3456) * 4;   // 71,936 B
    const int SMEM_X = (12352 + WX * 3456) * 4;  // 104,704 B
    cudaFuncSetAttribute(k_attn_y, cudaFuncAttributeMaxDynamicSharedMemorySize, SMEM_Y);
    cudaFuncSetAttribute(k_attn_x, cudaFuncAttributeMaxDynamicSharedMemorySize, SMEM_X);

    k_emb<<<B * 96, 256>>>(x, pos);
    k_attn_x<<<(B * 3) / WX, WX * 32, SMEM_X>>>(Wqx, W0x, gx, bx);
    k_attn_y<<<B * 24, WY * 32, SMEM_Y>>>(Wqy, W0y, gy, by);
    k_final<<<B * 96, 256>>>(x, out);
}

// round 2
// speedup vs baseline: 1.0059x; 1.0059x over previous
#include <cuda_runtime.h>

typedef unsigned long long u64;

#define B_MAX 256

// Scratch (static device globals — no allocation in kernel_launch)
__device__ float g_emb[B_MAX * 3 * 32 * 32 * 32];  // [b][c][i][t][j]
__device__ float g_sig[B_MAX * 3 * 32 * 32 * 32];  // sigmoid(LN(y-branch)) [b][c][i][t][j]
__device__ float g_sg2[B_MAX * 3 * 32 * 32];       // sigmoid(LN(x-branch)) [b][c][tok][feat]

// ---------------- packed f32x2 helpers (sm_103a FFMA2 path) ----------------
__device__ __forceinline__ u64 pack2(float lo, float hi) {
    u64 r; asm("mov.b64 %0, {%1, %2};" : "=l"(r) : "f"(lo), "f"(hi)); return r;
}
__device__ __forceinline__ void unpack2(u64 v, float& lo, float& hi) {
    asm("mov.b64 {%0, %1}, %2;" : "=f"(lo), "=f"(hi) : "l"(v));
}
__device__ __forceinline__ u64 fma2(u64 a, u64 b, u64 c) {
    u64 d; asm("fma.rn.f32x2 %0, %1, %2, %3;" : "=l"(d) : "l"(a), "l"(b), "l"(c)); return d;
}
__device__ __forceinline__ u64 mul2(u64 a, u64 b) {
    u64 d; asm("mul.rn.f32x2 %0, %1, %2;" : "=l"(d) : "l"(a), "l"(b)); return d;
}
__device__ __forceinline__ float sigmoid_(float v) { return 1.0f / (1.0f + __expf(-v)); }

// ---------------------------------------------------------------------------
// K1: emb[b,c,i,t,j] = sum_d x[b,c,t,d,i] * pos_y[c,j,d]
// ---------------------------------------------------------------------------
__global__ void __launch_bounds__(256) k_emb(const float* __restrict__ x,
                                             const float* __restrict__ pos)
{
    __shared__ float xs[32 * 33]; // xs[d][i]
    __shared__ float ps[32 * 36]; // ps[j][d]

    int bct = blockIdx.x;
    int t   = bct & 31;
    int bc  = bct >> 5;
    int c   = bc % 3;
    int tid = threadIdx.x;

    float4 xv = ((const float4*)(x + (size_t)bct * 1024))[tid];
    int rd = tid >> 3, c0 = (tid & 7) * 4;
    xs[rd * 33 + c0 + 0] = xv.x; xs[rd * 33 + c0 + 1] = xv.y;
    xs[rd * 33 + c0 + 2] = xv.z; xs[rd * 33 + c0 + 3] = xv.w;

    float4 pv = ((const float4*)(pos + c * 1024))[tid];
    ps[rd * 36 + c0 + 0] = pv.x; ps[rd * 36 + c0 + 1] = pv.y;
    ps[rd * 36 + c0 + 2] = pv.z; ps[rd * 36 + c0 + 3] = pv.w;
    __syncthreads();

    int i = tid >> 3, j0 = (tid & 7) * 4;
    float xc[32];
#pragma unroll
    for (int d = 0; d < 32; d++) xc[d] = xs[d * 33 + i];

    float a0 = 0.f, a1 = 0.f, a2 = 0.f, a3 = 0.f;
#pragma unroll
    for (int d4 = 0; d4 < 8; d4++) {
        float4 p;
        p = *(const float4*)(ps + (j0 + 0) * 36 + 4 * d4);
        a0 = fmaf(xc[4*d4], p.x, a0); a0 = fmaf(xc[4*d4+1], p.y, a0);
        a0 = fmaf(xc[4*d4+2], p.z, a0); a0 = fmaf(xc[4*d4+3], p.w, a0);
        p = *(const float4*)(ps + (j0 + 1) * 36 + 4 * d4);
        a1 = fmaf(xc[4*d4], p.x, a1); a1 = fmaf(xc[4*d4+1], p.y, a1);
        a1 = fmaf(xc[4*d4+2], p.z, a1); a1 = fmaf(xc[4*d4+3], p.w, a1);
        p = *(const float4*)(ps + (j0 + 2) * 36 + 4 * d4);
        a2 = fmaf(xc[4*d4], p.x, a2); a2 = fmaf(xc[4*d4+1], p.y, a2);
        a2 = fmaf(xc[4*d4+2], p.z, a2); a2 = fmaf(xc[4*d4+3], p.w, a2);
        p = *(const float4*)(ps + (j0 + 3) * 36 + 4 * d4);
        a3 = fmaf(xc[4*d4], p.x, a3); a3 = fmaf(xc[4*d4+1], p.y, a3);
        a3 = fmaf(xc[4*d4+2], p.z, a3); a3 = fmaf(xc[4*d4+3], p.w, a3);
    }
    float4 ov = make_float4(a0, a1, a2, a3);
    *(float4*)(g_emb + ((size_t)bc * 32 + i) * 1024 + t * 32 + j0) = ov;
}

// ---------------------------------------------------------------------------
// Warp attention, per-head streaming, packed f32x2 math.
// lane = token t. D=32, H=8, DH=4.
// skv: per-warp 32 rows x 12 floats (k4 at +0, v4 at +4, 4 pad).
// ---------------------------------------------------------------------------
__device__ __forceinline__ void warp_attn(
    int lane,
    const float* __restrict__ eg,   // E tile [t][j] row-major, 32x32
    float* __restrict__ og,         // output tile [t][j]
    const float* __restrict__ sW,   // Wqvk [96][32] in smem
    const float* __restrict__ sW0,  // W0 [32][32] in smem
    const float* __restrict__ sgb,  // gamma[32], beta[32]
    float* __restrict__ skv)        // 384 floats, warp-private
{
    // own token row -> packed registers
    u64 e2[16];
    {
        const ulonglong2* ep = (const ulonglong2*)(eg + lane * 32);
#pragma unroll
        for (int j = 0; j < 8; j++) { ulonglong2 v = ep[j]; e2[2*j] = v.x; e2[2*j+1] = v.y; }
    }
    // residual accumulator starts at E
    float rr[32];
#pragma unroll
    for (int j = 0; j < 16; j++) unpack2(e2[j], rr[2*j], rr[2*j+1]);

#pragma unroll 1
    for (int h = 0; h < 8; h++) {
        // ---- q,k,v for head h (rows f = d*24 + which*8 + h) ----
        float q[4], kk[4], vv[4];
#pragma unroll
        for (int d = 0; d < 4; d++) {
            const ulonglong2* wq = (const ulonglong2*)(sW + (d * 24 + h)      * 32);
            const ulonglong2* wk = (const ulonglong2*)(sW + (d * 24 + 8 + h)  * 32);
            const ulonglong2* wv = (const ulonglong2*)(sW + (d * 24 + 16 + h) * 32);
            u64 aq = 0, ak = 0, av = 0;
#pragma unroll
            for (int j = 0; j < 8; j++) {
                ulonglong2 w;
                w = wq[j]; aq = fma2(e2[2*j+1], w.y, fma2(e2[2*j], w.x, aq));
                w = wk[j]; ak = fma2(e2[2*j+1], w.y, fma2(e2[2*j], w.x, ak));
                w = wv[j]; av = fma2(e2[2*j+1], w.y, fma2(e2[2*j], w.x, av));
            }
            float a, b;
            unpack2(aq, a, b); q[d]  = (a + b) * 0.5f;   // fold DH^-0.5
            unpack2(ak, a, b); kk[d] = a + b;
            unpack2(av, a, b); vv[d] = a + b;
        }
        *(float4*)(skv + lane * 12)     = make_float4(kk[0], kk[1], kk[2], kk[3]);
        *(float4*)(skv + lane * 12 + 4) = make_float4(vv[0], vv[1], vv[2], vv[3]);
        u64 q01 = pack2(q[0], q[1]), q23 = pack2(q[2], q[3]);
        __syncwarp();

        // ---- fused softmax + AV (no max-subtract: |scores| << 88) ----
        float sum = 0.f;
        u64 a01 = 0, a23 = 0;
#pragma unroll
        for (int s = 0; s < 32; s++) {
            ulonglong2 k2 = *(const ulonglong2*)(skv + s * 12);
            ulonglong2 v2 = *(const ulonglong2*)(skv + s * 12 + 4);
            u64 t = fma2(q23, k2.y, mul2(q01, k2.x));
            float ta, tb; unpack2(t, ta, tb);
            float p = __expf(ta + tb);
            sum += p;
            u64 p2 = pack2(p, p);
            a01 = fma2(p2, v2.x, a01);
            a23 = fma2(p2, v2.y, a23);
        }
        __syncwarp();

        float inv = 1.f / sum;
        float oa, ob, oc, od;
        unpack2(a01, oa, ob); unpack2(a23, oc, od);
        u64 o01 = pack2(oa * inv, ob * inv), o23 = pack2(oc * inv, od * inv);

        // ---- incremental output projection: rr[j] += o_h . W0[j][4h..4h+3] ----
        const float* w0h = sW0 + 4 * h;
#pragma unroll
        for (int j = 0; j < 32; j += 2) {
            ulonglong2 wa = *(const ulonglong2*)(w0h + j * 32);
            ulonglong2 wb = *(const ulonglong2*)(w0h + (j + 1) * 32);
            u64 ra = fma2(o23, wa.y, mul2(o01, wa.x));
            u64 rb = fma2(o23, wb.y, mul2(o01, wb.x));
            float xa, xb;
            unpack2(ra, xa, xb); rr[j]     += xa + xb;
            unpack2(rb, xa, xb); rr[j + 1] += xa + xb;
        }
    }

    // ---- layernorm + sigmoid + store ----
    float s1 = 0.f;
#pragma unroll
    for (int j = 0; j < 32; j++) s1 += rr[j];
    float mu = s1 * 0.03125f;
    float sq = 0.f;
#pragma unroll
    for (int j = 0; j < 32; j++) { float d = rr[j] - mu; sq = fmaf(d, d, sq); }
    float rstd = rsqrtf(sq * 0.03125f + 1e-5f);

    float* po = og + lane * 32;
#pragma unroll
    for (int j = 0; j < 32; j += 4) {
        float4 v;
        v.x = sigmoid_((rr[j]     - mu) * rstd * sgb[j]     + sgb[32 + j]);
        v.y = sigmoid_((rr[j + 1] - mu) * rstd * sgb[j + 1] + sgb[33 + j]);
        v.z = sigmoid_((rr[j + 2] - mu) * rstd * sgb[j + 2] + sgb[34 + j]);
        v.w = sigmoid_((rr[j + 3] - mu) * rstd * sgb[j + 3] + sgb[35 + j]);
        *(float4*)(po + j) = v;
    }
}

// ---------------------------------------------------------------------------
// K2: x-branch. 1 warp per (b,c) on emb_last = emb[b,2,31]. Writes g_sg2.
// ---------------------------------------------------------------------------
#define WX 4
__global__ void __launch_bounds__(WX * 32) k_attn_x(
    const float* __restrict__ Wqvk, const float* __restrict__ W0,
    const float* __restrict__ g, const float* __restrict__ b)
{
    extern __shared__ float sm[];
    float* sW3  = sm;             // 3 * 3072
    float* sW03 = sm + 9216;      // 3 * 1024
    float* sgb  = sm + 12288;     // 64
    float* tiles = sm + 12352;    // WX * 384

    int tid = threadIdx.x;
    int w = tid >> 5, lane = tid & 31;
    for (int k = tid; k < 2304; k += WX * 32) ((float4*)sW3)[k]  = ((const float4*)Wqvk)[k];
    for (int k = tid; k < 768;  k += WX * 32) ((float4*)sW03)[k] = ((const float4*)W0)[k];
    if (tid < 32) { sgb[tid] = g[tid]; sgb[32 + tid] = b[tid]; }
    __syncthreads();

    int lin = blockIdx.x * WX + w;   // b*3 + c
    int bb = lin / 3, c = lin % 3;
    const float* eg = g_emb + (((size_t)bb * 3 + 2) * 32 + 31) * 1024;
    float* og = g_sg2 + (size_t)lin * 1024;
    warp_attn(lane, eg, og, sW3 + c * 3072, sW03 + c * 1024, sgb, tiles + w * 384);
}

// ---------------------------------------------------------------------------
// K3: y-branch. 1 warp per (b,c,i). Writes g_sig.
// ---------------------------------------------------------------------------
#define WY 4
__global__ void __launch_bounds__(WY * 32) k_attn_y(
    const float* __restrict__ Wqvk, const float* __restrict__ W0,
    const float* __restrict__ g, const float* __restrict__ b)
{
    __shared__ float sm[4160 + WY * 384];
    float* sW  = sm;            // 3072
    float* sW0 = sm + 3072;     // 1024
    float* sgb = sm + 4096;     // 64
    float* tiles = sm + 4160;

    int tid = threadIdx.x;
    int w = tid >> 5, lane = tid & 31;
    int bc = blockIdx.x >> 3;
    int iblk = blockIdx.x & 7;
    int c = bc % 3;

    for (int k = tid; k < 768; k += WY * 32) ((float4*)sW)[k]  = ((const float4*)(Wqvk + c * 3072))[k];
    for (int k = tid; k < 256; k += WY * 32) ((float4*)sW0)[k] = ((const float4*)(W0 + c * 1024))[k];
    if (tid < 32) { sgb[tid] = g[tid]; sgb[32 + tid] = b[tid]; }
    __syncthreads();

    int i = iblk * WY + w;
    const float* eg = g_emb + ((size_t)bc * 32 + i) * 1024;
    float* og       = g_sig + ((size_t)bc * 32 + i) * 1024;
    warp_attn(lane, eg, og, sW, sW0, sgb, tiles + w * 384);
}

// ---------------------------------------------------------------------------
// K4: final gated product (unchanged — at DRAM roofline)
// ---------------------------------------------------------------------------
__global__ void __launch_bounds__(256) k_final(const float* __restrict__ x,
                                               float* __restrict__ out)
{
    __shared__ float gs[32 * 33]; // gs[i][j]
    __shared__ float ss[32];
    int bct = blockIdx.x;
    int t = bct & 31;
    int bc = bct >> 5;
    int tid = threadIdx.x;

    int i = tid >> 3, j0 = (tid & 7) * 4;
    float4 gv = *(const float4*)(g_sig + ((size_t)bc * 32 + i) * 1024 + t * 32 + j0);
    gs[i * 33 + j0 + 0] = gv.x; gs[i * 33 + j0 + 1] = gv.y;
    gs[i * 33 + j0 + 2] = gv.z; gs[i * 33 + j0 + 3] = gv.w;
    if (tid < 32) ss[tid] = g_sg2[(size_t)bc * 1024 + tid * 32 + t];
    __syncthreads();

    float4 xv = ((const float4*)(x + (size_t)bct * 1024))[tid];
    int jj = tid >> 3, i0 = (tid & 7) * 4;
    float4 ov;
    ov.x = ss[i0 + 0] * gs[(i0 + 0) * 33 + jj] * xv.x;
    ov.y = ss[i0 + 1] * gs[(i0 + 1) * 33 + jj] * xv.y;
    ov.z = ss[i0 + 2] * gs[(i0 + 2) * 33 + jj] * xv.z;
    ov.w = ss[i0 + 3] * gs[(i0 + 3) * 33 + jj] * xv.w;
    ((float4*)(out + (size_t)bct * 1024))[tid] = ov;
}

// ---------------------------------------------------------------------------
extern "C" void kernel_launch(void* const* d_in, const int* in_sizes, int n_in,
                              void* d_out, int out_size)
{
    const float* x   = (const float*)d_in[0];
    const float* pos = (const float*)d_in[1];
    const float* Wqy = (const float*)d_in[2];
    const float* W0y = (const float*)d_in[3];
    const float* gy  = (const float*)d_in[4];
    const float* by  = (const float*)d_in[5];
    const float* Wqx = (const float*)d_in[6];
    const float* W0x = (const float*)d_in[7];
    const float* gx  = (const float*)d_in[8];
    const float* bx  = (const float*)d_in[9];
    float* out = (float*)d_out;

    int B = in_sizes[0] / 98304;  // 3*32*32*32

    const int SMEM_X = (12352 + WX * 384) * 4;  // 55,552 B
    cudaFuncSetAttribute(k_attn_x, cudaFuncAttributeMaxDynamicSharedMemorySize, SMEM_X);

    k_emb<<<B * 96, 256>>>(x, pos);
    k_attn_x<<<(B * 3) / WX, WX * 32, SMEM_X>>>(Wqx, W0x, gx, bx);
    k_attn_y<<<B * 24, WY * 32>>>(Wqy, W0y, gy, by);
    k_final<<<B * 96, 256>>>(x, out);
}

// round 3
// speedup vs baseline: 1.0388x; 1.0327x over previous
#include <cuda_runtime.h>

typedef unsigned long long u64;

#define B_MAX 256

// Scratch (static device globals — no allocation in kernel_launch)
__device__ float g_emb[B_MAX * 3 * 32 * 32 * 32];  // [b][c][i][t][j]
__device__ float g_sig[B_MAX * 3 * 32 * 32 * 32];  // y-branch RAW W0 projection [b][c][i][t][j]
__device__ float g_sg2[B_MAX * 3 * 32 * 32];       // sigmoid(LN(x-branch)) [b][c][tok][feat]

// ---------------- packed f32x2 helpers (sm_103a FFMA2 path) ----------------
__device__ __forceinline__ u64 pack2(float lo, float hi) {
    u64 r; asm("mov.b64 %0, {%1, %2};" : "=l"(r) : "f"(lo), "f"(hi)); return r;
}
__device__ __forceinline__ void unpack2(u64 v, float& lo, float& hi) {
    asm("mov.b64 {%0, %1}, %2;" : "=f"(lo), "=f"(hi) : "l"(v));
}
__device__ __forceinline__ u64 fma2(u64 a, u64 b, u64 c) {
    u64 d; asm("fma.rn.f32x2 %0, %1, %2, %3;" : "=l"(d) : "l"(a), "l"(b), "l"(c)); return d;
}
__device__ __forceinline__ u64 mul2(u64 a, u64 b) {
    u64 d; asm("mul.rn.f32x2 %0, %1, %2;" : "=l"(d) : "l"(a), "l"(b)); return d;
}
__device__ __forceinline__ float sigmoid_(float v) { return 1.0f / (1.0f + __expf(-v)); }

// ---------------------------------------------------------------------------
// K1: emb[b,c,i,t,j] = sum_d x[b,c,t,d,i] * pos_y[c,j,d]
// ---------------------------------------------------------------------------
__global__ void __launch_bounds__(256) k_emb(const float* __restrict__ x,
                                             const float* __restrict__ pos)
{
    __shared__ float xs[32 * 33]; // xs[d][i]
    __shared__ float ps[32 * 36]; // ps[j][d]

    int bct = blockIdx.x;
    int t   = bct & 31;
    int bc  = bct >> 5;
    int c   = bc % 3;
    int tid = threadIdx.x;

    float4 xv = ((const float4*)(x + (size_t)bct * 1024))[tid];
    int rd = tid >> 3, c0 = (tid & 7) * 4;
    xs[rd * 33 + c0 + 0] = xv.x; xs[rd * 33 + c0 + 1] = xv.y;
    xs[rd * 33 + c0 + 2] = xv.z; xs[rd * 33 + c0 + 3] = xv.w;

    float4 pv = ((const float4*)(pos + c * 1024))[tid];
    ps[rd * 36 + c0 + 0] = pv.x; ps[rd * 36 + c0 + 1] = pv.y;
    ps[rd * 36 + c0 + 2] = pv.z; ps[rd * 36 + c0 + 3] = pv.w;
    __syncthreads();

    int i = tid >> 3, j0 = (tid & 7) * 4;
    float xc[32];
#pragma unroll
    for (int d = 0; d < 32; d++) xc[d] = xs[d * 33 + i];

    float a0 = 0.f, a1 = 0.f, a2 = 0.f, a3 = 0.f;
#pragma unroll
    for (int d4 = 0; d4 < 8; d4++) {
        float4 p;
        p = *(const float4*)(ps + (j0 + 0) * 36 + 4 * d4);
        a0 = fmaf(xc[4*d4], p.x, a0); a0 = fmaf(xc[4*d4+1], p.y, a0);
        a0 = fmaf(xc[4*d4+2], p.z, a0); a0 = fmaf(xc[4*d4+3], p.w, a0);
        p = *(const float4*)(ps + (j0 + 1) * 36 + 4 * d4);
        a1 = fmaf(xc[4*d4], p.x, a1); a1 = fmaf(xc[4*d4+1], p.y, a1);
        a1 = fmaf(xc[4*d4+2], p.z, a1); a1 = fmaf(xc[4*d4+3], p.w, a1);
        p = *(const float4*)(ps + (j0 + 2) * 36 + 4 * d4);
        a2 = fmaf(xc[4*d4], p.x, a2); a2 = fmaf(xc[4*d4+1], p.y, a2);
        a2 = fmaf(xc[4*d4+2], p.z, a2); a2 = fmaf(xc[4*d4+3], p.w, a2);
        p = *(const float4*)(ps + (j0 + 3) * 36 + 4 * d4);
        a3 = fmaf(xc[4*d4], p.x, a3); a3 = fmaf(xc[4*d4+1], p.y, a3);
        a3 = fmaf(xc[4*d4+2], p.z, a3); a3 = fmaf(xc[4*d4+3], p.w, a3);
    }
    float4 ov = make_float4(a0, a1, a2, a3);
    *(float4*)(g_emb + ((size_t)bc * 32 + i) * 1024 + t * 32 + j0) = ov;
}

// ---------------------------------------------------------------------------
// y-branch warp attention: emits RAW W0 projection (no residual/LN/sigmoid).
// Low register footprint: no persistent accumulator; per-head o -> smem.
// swk: per-warp 1408 floats: [0..384) kv (32 rows x 12), [384..1408) o (32x32).
// Staging (32x33=1056 floats) overlays swk after o reload.
// ---------------------------------------------------------------------------
__device__ __forceinline__ void warp_attn_y(
    int lane,
    const float* __restrict__ eg,   // E tile [t][j], 32x32
    float* __restrict__ og,         // proj output [t][j]
    const float* __restrict__ sW,   // Wqvk [96][32]
    const float* __restrict__ sW0,  // W0 [32][32]
    float* __restrict__ swk)
{
    float* skv = swk;
    float* so  = swk + 384;

    u64 e2[16];
    {
        const ulonglong2* ep = (const ulonglong2*)(eg + lane * 32);
#pragma unroll
        for (int j = 0; j < 8; j++) { ulonglong2 v = ep[j]; e2[2*j] = v.x; e2[2*j+1] = v.y; }
    }

#pragma unroll 1
    for (int h = 0; h < 8; h++) {
        // ---- q,k,v for head h ----
        float q[4], kk[4], vv[4];
#pragma unroll
        for (int d = 0; d < 4; d++) {
            const ulonglong2* wq = (const ulonglong2*)(sW + (d * 24 + h)      * 32);
            const ulonglong2* wk = (const ulonglong2*)(sW + (d * 24 + 8 + h)  * 32);
            const ulonglong2* wv = (const ulonglong2*)(sW + (d * 24 + 16 + h) * 32);
            u64 aq = 0, ak = 0, av = 0;
#pragma unroll
            for (int j = 0; j < 8; j++) {
                ulonglong2 w;
                w = wq[j]; aq = fma2(e2[2*j+1], w.y, fma2(e2[2*j], w.x, aq));
                w = wk[j]; ak = fma2(e2[2*j+1], w.y, fma2(e2[2*j], w.x, ak));
                w = wv[j]; av = fma2(e2[2*j+1], w.y, fma2(e2[2*j], w.x, av));
            }
            float a, b;
            unpack2(aq, a, b); q[d]  = (a + b) * 0.5f;   // fold DH^-0.5
            unpack2(ak, a, b); kk[d] = a + b;
            unpack2(av, a, b); vv[d] = a + b;
        }
        *(float4*)(skv + lane * 12)     = make_float4(kk[0], kk[1], kk[2], kk[3]);
        *(float4*)(skv + lane * 12 + 4) = make_float4(vv[0], vv[1], vv[2], vv[3]);
        u64 q01 = pack2(q[0], q[1]), q23 = pack2(q[2], q[3]);
        __syncwarp();

        // ---- fused softmax + AV ----
        float sum = 0.f;
        u64 a01 = 0, a23 = 0;
#pragma unroll
        for (int s = 0; s < 32; s++) {
            ulonglong2 k2 = *(const ulonglong2*)(skv + s * 12);
            ulonglong2 v2 = *(const ulonglong2*)(skv + s * 12 + 4);
            u64 t = fma2(q23, k2.y, mul2(q01, k2.x));
            float ta, tb; unpack2(t, ta, tb);
            float p = __expf(ta + tb);
            sum += p;
            u64 p2 = pack2(p, p);
            a01 = fma2(p2, v2.x, a01);
            a23 = fma2(p2, v2.y, a23);
        }
        float inv = 1.f / sum;
        float oa, ob, oc, od;
        unpack2(a01, oa, ob); unpack2(a23, oc, od);
        *(float4*)(so + lane * 32 + 4 * h) =
            make_float4(oa * inv, ob * inv, oc * inv, od * inv);
        __syncwarp();  // all lanes done reading skv before next head overwrites
    }

    // ---- reload o row, W0 GEMV, transposed staging, coalesced store ----
    u64 o2[16];
    {
        const ulonglong2* op = (const ulonglong2*)(so + lane * 32);
#pragma unroll
        for (int j = 0; j < 8; j++) { ulonglong2 v = op[j]; o2[2*j] = v.x; o2[2*j+1] = v.y; }
    }
    __syncwarp();  // everyone reloaded before staging overwrites so/skv

    float* st = swk;  // 32 x 33 staging
#pragma unroll
    for (int j = 0; j < 32; j += 2) {
        const ulonglong2* wa = (const ulonglong2*)(sW0 + j * 32);
        const ulonglong2* wb = (const ulonglong2*)(sW0 + (j + 1) * 32);
        u64 ra = 0, rb = 0;
#pragma unroll
        for (int m = 0; m < 4; m++) {
            ulonglong2 w;
            w = wa[m]; ra = fma2(o2[2*m+1], w.y, fma2(o2[2*m], w.x, ra));
            w = wb[m]; rb = fma2(o2[2*m+1], w.y, fma2(o2[2*m], w.x, rb));
        }
#pragma unroll
        for (int m = 4; m < 8; m++) {
            ulonglong2 w;
            w = wa[m]; ra = fma2(o2[2*m+1], w.y, fma2(o2[2*m], w.x, ra));
            w = wb[m]; rb = fma2(o2[2*m+1], w.y, fma2(o2[2*m], w.x, rb));
        }
        float xa, xb;
        unpack2(ra, xa, xb); st[lane * 33 + j]     = xa + xb;
        unpack2(rb, xa, xb); st[lane * 33 + j + 1] = xa + xb;
    }
    __syncwarp();

#pragma unroll
    for (int r = 0; r < 32; r++) og[r * 32 + lane] = st[r * 33 + lane];
}

// ---------------------------------------------------------------------------
// x-branch full warp attention (with residual + LN + sigmoid) — small kernel.
// ---------------------------------------------------------------------------
__device__ __forceinline__ void warp_attn_full(
    int lane,
    const float* __restrict__ eg, float* __restrict__ og,
    const float* __restrict__ sW, const float* __restrict__ sW0,
    const float* __restrict__ sgb, float* __restrict__ skv)
{
    u64 e2[16];
    {
        const ulonglong2* ep = (const ulonglong2*)(eg + lane * 32);
#pragma unroll
        for (int j = 0; j < 8; j++) { ulonglong2 v = ep[j]; e2[2*j] = v.x; e2[2*j+1] = v.y; }
    }
    float rr[32];
#pragma unroll
    for (int j = 0; j < 16; j++) unpack2(e2[j], rr[2*j], rr[2*j+1]);

#pragma unroll 1
    for (int h = 0; h < 8; h++) {
        float q[4], kk[4], vv[4];
#pragma unroll
        for (int d = 0; d < 4; d++) {
            const ulonglong2* wq = (const ulonglong2*)(sW + (d * 24 + h)      * 32);
            const ulonglong2* wk = (const ulonglong2*)(sW + (d * 24 + 8 + h)  * 32);
            const ulonglong2* wv = (const ulonglong2*)(sW + (d * 24 + 16 + h) * 32);
            u64 aq = 0, ak = 0, av = 0;
#pragma unroll
            for (int j = 0; j < 8; j++) {
                ulonglong2 w;
                w = wq[j]; aq = fma2(e2[2*j+1], w.y, fma2(e2[2*j], w.x, aq));
                w = wk[j]; ak = fma2(e2[2*j+1], w.y, fma2(e2[2*j], w.x, ak));
                w = wv[j]; av = fma2(e2[2*j+1], w.y, fma2(e2[2*j], w.x, av));
            }
            float a, b;
            unpack2(aq, a, b); q[d]  = (a + b) * 0.5f;
            unpack2(ak, a, b); kk[d] = a + b;
            unpack2(av, a, b); vv[d] = a + b;
        }
        *(float4*)(skv + lane * 12)     = make_float4(kk[0], kk[1], kk[2], kk[3]);
        *(float4*)(skv + lane * 12 + 4) = make_float4(vv[0], vv[1], vv[2], vv[3]);
        u64 q01 = pack2(q[0], q[1]), q23 = pack2(q[2], q[3]);
        __syncwarp();

        float sum = 0.f;
        u64 a01 = 0, a23 = 0;
#pragma unroll
        for (int s = 0; s < 32; s++) {
            ulonglong2 k2 = *(const ulonglong2*)(skv + s * 12);
            ulonglong2 v2 = *(const ulonglong2*)(skv + s * 12 + 4);
            u64 t = fma2(q23, k2.y, mul2(q01, k2.x));
            float ta, tb; unpack2(t, ta, tb);
            float p = __expf(ta + tb);
            sum += p;
            u64 p2 = pack2(p, p);
            a01 = fma2(p2, v2.x, a01);
            a23 = fma2(p2, v2.y, a23);
        }
        __syncwarp();
        float inv = 1.f / sum;
        float oa, ob, oc, od;
        unpack2(a01, oa, ob); unpack2(a23, oc, od);
        u64 o01 = pack2(oa * inv, ob * inv), o23 = pack2(oc * inv, od * inv);

        const float* w0h = sW0 + 4 * h;
#pragma unroll
        for (int j = 0; j < 32; j += 2) {
            ulonglong2 wa = *(const ulonglong2*)(w0h + j * 32);
            ulonglong2 wb = *(const ulonglong2*)(w0h + (j + 1) * 32);
            u64 ra = fma2(o23, wa.y, mul2(o01, wa.x));
            u64 rb = fma2(o23, wb.y, mul2(o01, wb.x));
            float xa, xb;
            unpack2(ra, xa, xb); rr[j]     += xa + xb;
            unpack2(rb, xa, xb); rr[j + 1] += xa + xb;
        }
    }

    float s1 = 0.f;
#pragma unroll
    for (int j = 0; j < 32; j++) s1 += rr[j];
    float mu = s1 * 0.03125f;
    float sq = 0.f;
#pragma unroll
    for (int j = 0; j < 32; j++) { float d = rr[j] - mu; sq = fmaf(d, d, sq); }
    float rstd = rsqrtf(sq * 0.03125f + 1e-5f);

    float* po = og + lane * 32;
#pragma unroll
    for (int j = 0; j < 32; j += 4) {
        float4 v;
        v.x = sigmoid_((rr[j]     - mu) * rstd * sgb[j]     + sgb[32 + j]);
        v.y = sigmoid_((rr[j + 1] - mu) * rstd * sgb[j + 1] + sgb[33 + j]);
        v.z = sigmoid_((rr[j + 2] - mu) * rstd * sgb[j + 2] + sgb[34 + j]);
        v.w = sigmoid_((rr[j + 3] - mu) * rstd * sgb[j + 3] + sgb[35 + j]);
        *(float4*)(po + j) = v;
    }
}

// ---------------------------------------------------------------------------
// K2: x-branch. 1 warp per (b,c) on emb_last = emb[b,2,31]. Writes g_sg2.
// ---------------------------------------------------------------------------
#define WX 4
__global__ void __launch_bounds__(WX * 32) k_attn_x(
    const float* __restrict__ Wqvk, const float* __restrict__ W0,
    const float* __restrict__ g, const float* __restrict__ b)
{
    extern __shared__ float sm[];
    float* sW3  = sm;             // 3 * 3072
    float* sW03 = sm + 9216;      // 3 * 1024
    float* sgb  = sm + 12288;     // 64
    float* tiles = sm + 12352;    // WX * 384

    int tid = threadIdx.x;
    int w = tid >> 5, lane = tid & 31;
    for (int k = tid; k < 2304; k += WX * 32) ((float4*)sW3)[k]  = ((const float4*)Wqvk)[k];
    for (int k = tid; k < 768;  k += WX * 32) ((float4*)sW03)[k] = ((const float4*)W0)[k];
    if (tid < 32) { sgb[tid] = g[tid]; sgb[32 + tid] = b[tid]; }
    __syncthreads();

    int lin = blockIdx.x * WX + w;   // b*3 + c
    int bb = lin / 3, c = lin % 3;
    const float* eg = g_emb + (((size_t)bb * 3 + 2) * 32 + 31) * 1024;
    float* og = g_sg2 + (size_t)lin * 1024;
    warp_attn_full(lane, eg, og, sW3 + c * 3072, sW03 + c * 1024, sgb, tiles + w * 384);
}

// ---------------------------------------------------------------------------
// K3: y-branch. 1 warp per (b,c,i). Writes raw projection to g_sig.
// ---------------------------------------------------------------------------
#define WY 4
__global__ void __launch_bounds__(WY * 32, 5) k_attn_y(
    const float* __restrict__ Wqvk, const float* __restrict__ W0)
{
    __shared__ float sm[4096 + WY * 1408];
    float* sW  = sm;            // 3072
    float* sW0 = sm + 3072;     // 1024
    float* tiles = sm + 4096;

    int tid = threadIdx.x;
    int w = tid >> 5, lane = tid & 31;
    int bc = blockIdx.x >> 3;
    int iblk = blockIdx.x & 7;
    int c = bc % 3;

    for (int k = tid; k < 768; k += WY * 32) ((float4*)sW)[k]  = ((const float4*)(Wqvk + c * 3072))[k];
    for (int k = tid; k < 256; k += WY * 32) ((float4*)sW0)[k] = ((const float4*)(W0 + c * 1024))[k];
    __syncthreads();

    int i = iblk * WY + w;
    const float* eg = g_emb + ((size_t)bc * 32 + i) * 1024;
    float* og       = g_sig + ((size_t)bc * 32 + i) * 1024;
    warp_attn_y(lane, eg, og, sW, sW0, tiles + w * 1408);
}

// ---------------------------------------------------------------------------
// K4: final. gate_y = sigmoid(LN(emb + proj)); out = sg2 * gate_y * x.
// CTA per (b,c,t). LN over j via 8-lane subwarp shuffle reduction.
// ---------------------------------------------------------------------------
__global__ void __launch_bounds__(256) k_final(const float* __restrict__ x,
                                               const float* __restrict__ gam,
                                               const float* __restrict__ bet,
                                               float* __restrict__ out)
{
    __shared__ float gs[32 * 33]; // gs[i][j] = gate
    __shared__ float ss[32];      // sg2 gate per i
    int bct = blockIdx.x;
    int t = bct & 31;
    int bc = bct >> 5;
    int tid = threadIdx.x;

    int i = tid >> 3, j0 = (tid & 7) * 4;
    size_t base = ((size_t)bc * 32 + i) * 1024 + t * 32 + j0;
    float4 pv = *(const float4*)(g_sig + base);
    float4 ev = *(const float4*)(g_emb + base);
    float4 v;
    v.x = pv.x + ev.x; v.y = pv.y + ev.y; v.z = pv.z + ev.z; v.w = pv.w + ev.w;

    float s1 = v.x + v.y + v.z + v.w;
    float s2 = fmaf(v.x, v.x, fmaf(v.y, v.y, fmaf(v.z, v.z, v.w * v.w)));
#pragma unroll
    for (int m = 1; m < 8; m <<= 1) {
        s1 += __shfl_xor_sync(0xffffffffu, s1, m);
        s2 += __shfl_xor_sync(0xffffffffu, s2, m);
    }
    float mu = s1 * 0.03125f;
    float var = fmaf(-mu, mu, s2 * 0.03125f);
    float rstd = rsqrtf(var + 1e-5f);

    float4 gm = *(const float4*)(gam + j0);
    float4 bt = *(const float4*)(bet + j0);
    gs[i * 33 + j0 + 0] = sigmoid_((v.x - mu) * rstd * gm.x + bt.x);
    gs[i * 33 + j0 + 1] = sigmoid_((v.y - mu) * rstd * gm.y + bt.y);
    gs[i * 33 + j0 + 2] = sigmoid_((v.z - mu) * rstd * gm.z + bt.z);
    gs[i * 33 + j0 + 3] = sigmoid_((v.w - mu) * rstd * gm.w + bt.w);
    if (tid < 32) ss[tid] = g_sg2[(size_t)bc * 1024 + tid * 32 + t];
    __syncthreads();

    float4 xv = ((const float4*)(x + (size_t)bct * 1024))[tid];
    int jj = tid >> 3, i0 = (tid & 7) * 4;
    float4 ov;
    ov.x = ss[i0 + 0] * gs[(i0 + 0) * 33 + jj] * xv.x;
    ov.y = ss[i0 + 1] * gs[(i0 + 1) * 33 + jj] * xv.y;
    ov.z = ss[i0 + 2] * gs[(i0 + 2) * 33 + jj] * xv.z;
    ov.w = ss[i0 + 3] * gs[(i0 + 3) * 33 + jj] * xv.w;
    ((float4*)(out + (size_t)bct * 1024))[tid] = ov;
}

// ---------------------------------------------------------------------------
extern "C" void kernel_launch(void* const* d_in, const int* in_sizes, int n_in,
                              void* d_out, int out_size)
{
    const float* x   = (const float*)d_in[0];
    const float* pos = (const float*)d_in[1];
    const float* Wqy = (const float*)d_in[2];
    const float* W0y = (const float*)d_in[3];
    const float* gy  = (const float*)d_in[4];
    const float* by  = (const float*)d_in[5];
    const float* Wqx = (const float*)d_in[6];
    const float* W0x = (const float*)d_in[7];
    const float* gx  = (const float*)d_in[8];
    const float* bx  = (const float*)d_in[9];
    float* out = (float*)d_out;

    int B = in_sizes[0] / 98304;  // 3*32*32*32

    const int SMEM_X = (12352 + WX * 384) * 4;
    cudaFuncSetAttribute(k_attn_x, cudaFuncAttributeMaxDynamicSharedMemorySize, SMEM_X);

    k_emb<<<B * 96, 256>>>(x, pos);
    k_attn_x<<<(B * 3) / WX, WX * 32, SMEM_X>>>(Wqx, W0x, gx, bx);
    k_attn_y<<<B * 24, WY * 32>>>(Wqy, W0y);
    k_final<<<B * 96, 256>>>(x, gy, by, out);
}